// round 6
// baseline (speedup 1.0000x reference)
#include <cuda_runtime.h>
#include <cstdint>

#define N_NODES 100000
#define N_EDGES 1600000
#define NF 128

// Scratch (allocation-free rule: __device__ globals). All atomics target
// these — NEVER the harness-owned d_out (atomics on it trap on GB300).
__device__ float g_h[(size_t)N_NODES * NF];     // h = x @ W
__device__ float g_out[(size_t)N_NODES * NF];   // accumulator for output
__device__ int   g_deg[N_NODES];
__device__ float g_dinv[N_NODES];
__device__ int   g_is64;                        // 1 if edge_index stored as int64

// ---------------------------------------------------------------------------
// 0) Detect index dtype layout. int64 values < 100000 have zero high words
//    (odd 32-bit positions). int32 random indices make odd words nonzero.
__global__ void detect_idx_kernel(const int* __restrict__ ei32) {
    if (threadIdx.x == 0) {
        int any_odd_nonzero = 0;
        #pragma unroll
        for (int i = 1; i < 64; i += 2) {
            if (ei32[i] != 0) any_odd_nonzero = 1;
        }
        g_is64 = any_odd_nonzero ? 0 : 1;
    }
}

// ---------------------------------------------------------------------------
// 1) init degree to 1 (self loop)
__global__ void init_deg_kernel() {
    int i = blockIdx.x * blockDim.x + threadIdx.x;
    if (i < N_NODES) g_deg[i] = 1;
}

// 2) count in-degree over edges (dst row of edge_index)
__global__ __launch_bounds__(256) void count_deg_kernel(const int* __restrict__ ei32) {
    const int is64 = g_is64;
    const int stride = is64 ? 2 : 1;
    const long long dstbase = is64 ? (2LL * N_EDGES) : (long long)N_EDGES;

    int base = 4 * (blockIdx.x * blockDim.x + threadIdx.x);
    #pragma unroll
    for (int j = 0; j < 4; j++) {
        int e = base + j;
        if (e < N_EDGES) {
            int d = ei32[dstbase + (long long)stride * e];
            atomicAdd(&g_deg[d], 1);
        }
    }
}

// 3) dinv = rsqrt(deg)   (deg >= 1 always due to self loop)
__global__ void dinv_kernel() {
    int i = blockIdx.x * blockDim.x + threadIdx.x;
    if (i < N_NODES) g_dinv[i] = rsqrtf((float)g_deg[i]);
}

// ---------------------------------------------------------------------------
// 4) GEMM: h = x @ W, fused epilogue:
//    g_out[i][c] = b[c] + dinv[i]^2 * h[i][c]   (self-loop contribution)
#define GEMM_ROWS 16
__global__ __launch_bounds__(128) void gemm_selfloop_kernel(
    const float* __restrict__ x, const float* __restrict__ W,
    const float* __restrict__ b)
{
    __shared__ float xs[GEMM_ROWS][NF];
    const int col  = threadIdx.x;            // 0..127
    const int row0 = blockIdx.x * GEMM_ROWS;

    #pragma unroll
    for (int r = 0; r < GEMM_ROWS; r++) {
        xs[r][col] = x[(size_t)(row0 + r) * NF + col];
    }
    __syncthreads();

    const float bc = b[col];

    #pragma unroll 2
    for (int r = 0; r < GEMM_ROWS; r++) {
        float acc = 0.0f;
        #pragma unroll
        for (int k = 0; k < NF; k++) {
            acc = fmaf(xs[r][k], W[(size_t)k * NF + col], acc);
        }
        const int row = row0 + r;
        g_h[(size_t)row * NF + col] = acc;
        const float di = g_dinv[row];
        g_out[(size_t)row * NF + col] = bc + di * di * acc;
    }
}

// ---------------------------------------------------------------------------
// 5) Edge scatter: one warp per edge. Each lane handles 4 contiguous feats.
//    g_out[dst] += h[src] * dinv[src] * dinv[dst]
__global__ __launch_bounds__(256) void scatter_kernel(const int* __restrict__ ei32)
{
    const unsigned long long tid =
        (unsigned long long)blockIdx.x * blockDim.x + threadIdx.x;
    const unsigned long long nwork = (unsigned long long)N_EDGES * 32ull;
    if (tid >= nwork) return;

    const int is64 = g_is64;
    const int stride = is64 ? 2 : 1;
    const long long dstbase = is64 ? (2LL * N_EDGES) : (long long)N_EDGES;

    const int e = (int)(tid >> 5);
    const int g = (int)(tid & 31);

    const int s = ei32[(long long)stride * e];
    const int d = ei32[dstbase + (long long)stride * e];
    const float norm = g_dinv[s] * g_dinv[d];

    const float4 hv = *reinterpret_cast<const float4*>(&g_h[(size_t)s * NF + g * 4]);
    float* o = &g_out[(size_t)d * NF + g * 4];
    atomicAdd(o + 0, hv.x * norm);
    atomicAdd(o + 1, hv.y * norm);
    atomicAdd(o + 2, hv.z * norm);
    atomicAdd(o + 3, hv.w * norm);
}

// ---------------------------------------------------------------------------
// 6) Final copy: d_out <- g_out (plain stores only; safe on any allocation)
__global__ __launch_bounds__(256) void copy_out_kernel(float* __restrict__ out) {
    const size_t i = ((size_t)blockIdx.x * blockDim.x + threadIdx.x) * 4;
    const size_t n = (size_t)N_NODES * NF;
    if (i < n) {
        *reinterpret_cast<float4*>(out + i) =
            *reinterpret_cast<const float4*>(&g_out[i]);
    }
}

// ---------------------------------------------------------------------------
extern "C" void kernel_launch(void* const* d_in, const int* in_sizes, int n_in,
                              void* d_out, int out_size) {
    const float* x    = (const float*)d_in[0];   // [N_NODES, NF]
    const int*   ei32 = (const int*)d_in[1];     // [2, N_EDGES] int32 (or int64)
    const float* W    = (const float*)d_in[2];   // [NF, NF]
    const float* b    = (const float*)d_in[3];   // [NF]
    float*       out  = (float*)d_out;           // [N_NODES, NF]

    detect_idx_kernel<<<1, 32>>>(ei32);
    init_deg_kernel<<<(N_NODES + 255) / 256, 256>>>();
    count_deg_kernel<<<(N_EDGES / 4 + 255) / 256, 256>>>(ei32);
    dinv_kernel<<<(N_NODES + 255) / 256, 256>>>();
    gemm_selfloop_kernel<<<N_NODES / GEMM_ROWS, 128>>>(x, W, b);
    {
        const unsigned long long nwork = (unsigned long long)N_EDGES * 32ull;
        const int threads = 256;
        const unsigned blocks = (unsigned)((nwork + threads - 1) / threads);
        scatter_kernel<<<blocks, threads>>>(ei32);
    }
    {
        const size_t nvec = ((size_t)N_NODES * NF) / 4;   // 3,200,000 float4s
        copy_out_kernel<<<(unsigned)((nvec + 255) / 256), 256>>>(out);
    }
}

// round 7
// speedup vs baseline: 2.1508x; 2.1508x over previous
#include <cuda_runtime.h>
#include <cstdint>

#define N_NODES 100000
#define N_EDGES 1600000
#define NF 128
#define SCAN_B 1024
#define SCAN_NBLK ((N_NODES + SCAN_B - 1) / SCAN_B)   // 98

// Scratch (__device__ globals only; no allocation anywhere).
__device__ float g_h[(size_t)N_NODES * NF];   // h = x @ W
__device__ int   g_cnt[N_NODES];              // edge in-degree (no self loop)
__device__ int   g_excl[N_NODES];             // per-block exclusive scan
__device__ int   g_blksum[SCAN_NBLK];
__device__ int   g_blkoff[SCAN_NBLK];
__device__ int   g_rowptr[N_NODES + 1];
__device__ int   g_cur[N_NODES];              // placement cursors
__device__ int   g_esrc[N_EDGES];             // CSR: src ids grouped by dst
__device__ float g_dinv[N_NODES];
__device__ int   g_is64;                      // 1 if edge_index stored as int64

// ---------------------------------------------------------------------------
// 0) Detect index dtype (int64 values < 100000 -> zero high words).
__global__ void detect_idx_kernel(const int* __restrict__ ei32) {
    if (threadIdx.x == 0) {
        int any_odd_nonzero = 0;
        #pragma unroll
        for (int i = 1; i < 64; i += 2)
            if (ei32[i] != 0) any_odd_nonzero = 1;
        g_is64 = any_odd_nonzero ? 0 : 1;
    }
}

// 1) zero edge counts
__global__ void zero_cnt_kernel() {
    int i = blockIdx.x * blockDim.x + threadIdx.x;
    if (i < N_NODES) g_cnt[i] = 0;
}

// 2) count in-degree over edges (dst row)
__global__ __launch_bounds__(256) void count_deg_kernel(const int* __restrict__ ei32) {
    const int stride = g_is64 ? 2 : 1;
    const long long dstbase = g_is64 ? (2LL * N_EDGES) : (long long)N_EDGES;
    int base = 4 * (blockIdx.x * blockDim.x + threadIdx.x);
    #pragma unroll
    for (int j = 0; j < 4; j++) {
        int e = base + j;
        if (e < N_EDGES)
            atomicAdd(&g_cnt[ei32[dstbase + (long long)stride * e]], 1);
    }
}

// 3a) per-block inclusive scan -> exclusive + block sums
__global__ __launch_bounds__(SCAN_B) void scan_a_kernel() {
    __shared__ int sd[SCAN_B];
    const int tid = threadIdx.x;
    const int i = blockIdx.x * SCAN_B + tid;
    int v = (i < N_NODES) ? g_cnt[i] : 0;
    sd[tid] = v;
    __syncthreads();
    #pragma unroll
    for (int off = 1; off < SCAN_B; off <<= 1) {
        int t = (tid >= off) ? sd[tid - off] : 0;
        __syncthreads();
        sd[tid] += t;
        __syncthreads();
    }
    if (i < N_NODES) g_excl[i] = sd[tid] - v;
    if (tid == SCAN_B - 1) g_blksum[blockIdx.x] = sd[tid];
}

// 3b) serial scan of 98 block sums (trivial)
__global__ void scan_b_kernel() {
    if (threadIdx.x == 0) {
        int run = 0;
        for (int k = 0; k < SCAN_NBLK; k++) { g_blkoff[k] = run; run += g_blksum[k]; }
    }
}

// 3c) finalize rowptr / cursors / dinv
__global__ void scan_c_kernel() {
    int i = blockIdx.x * blockDim.x + threadIdx.x;
    if (i < N_NODES) {
        int rp = g_excl[i] + g_blkoff[i >> 10];
        g_rowptr[i] = rp;
        g_cur[i] = rp;
        g_dinv[i] = rsqrtf((float)(g_cnt[i] + 1));   // +1 self loop
        if (i == 0) g_rowptr[N_NODES] = N_EDGES;
    }
}

// 4) placement: CSR src list grouped by dst
__global__ __launch_bounds__(256) void place_kernel(const int* __restrict__ ei32) {
    const int stride = g_is64 ? 2 : 1;
    const long long dstbase = g_is64 ? (2LL * N_EDGES) : (long long)N_EDGES;
    int base = 4 * (blockIdx.x * blockDim.x + threadIdx.x);
    #pragma unroll
    for (int j = 0; j < 4; j++) {
        int e = base + j;
        if (e < N_EDGES) {
            int s = ei32[(long long)stride * e];
            int d = ei32[dstbase + (long long)stride * e];
            int slot = atomicAdd(&g_cur[d], 1);
            g_esrc[slot] = s;
        }
    }
}

// ---------------------------------------------------------------------------
// 5) GEMM: g_h = x @ W
#define GEMM_ROWS 16
__global__ __launch_bounds__(128) void gemm_kernel(
    const float* __restrict__ x, const float* __restrict__ W)
{
    __shared__ float xs[GEMM_ROWS][NF];
    const int col  = threadIdx.x;
    const int row0 = blockIdx.x * GEMM_ROWS;

    #pragma unroll
    for (int r = 0; r < GEMM_ROWS; r++)
        xs[r][col] = x[(size_t)(row0 + r) * NF + col];
    __syncthreads();

    #pragma unroll 2
    for (int r = 0; r < GEMM_ROWS; r++) {
        float acc = 0.0f;
        #pragma unroll
        for (int k = 0; k < NF; k++)
            acc = fmaf(xs[r][k], W[(size_t)k * NF + col], acc);
        g_h[(size_t)(row0 + r) * NF + col] = acc;
    }
}

// ---------------------------------------------------------------------------
// 6) Gather: one block per dst node, thread = feature column. No atomics.
//    out[d][c] = b[c] + dinv[d] * ( sum_e h[src_e][c]*dinv[src_e]
//                                   + dinv[d]*h[d][c] )
#define ETILE 128
__global__ __launch_bounds__(128) void gather_kernel(
    const float* __restrict__ b, float* __restrict__ out)
{
    __shared__ int   ss[ETILE];
    __shared__ float sv[ETILE];

    const int d = blockIdx.x;
    const int c = threadIdx.x;
    const int start = g_rowptr[d];
    const int end   = g_rowptr[d + 1];
    const float dinv_d = g_dinv[d];

    float acc = dinv_d * g_h[(size_t)d * NF + c];   // self loop

    for (int t = start; t < end; t += ETILE) {
        const int n = min(ETILE, end - t);
        if (c < n) {
            int s = g_esrc[t + c];
            ss[c] = s;
            sv[c] = g_dinv[s];
        }
        __syncthreads();
        for (int j = 0; j < n; j++) {
            acc = fmaf(g_h[(size_t)ss[j] * NF + c], sv[j], acc);
        }
        __syncthreads();
    }

    out[(size_t)d * NF + c] = b[c] + dinv_d * acc;
}

// ---------------------------------------------------------------------------
extern "C" void kernel_launch(void* const* d_in, const int* in_sizes, int n_in,
                              void* d_out, int out_size) {
    const float* x    = (const float*)d_in[0];   // [N_NODES, NF]
    const int*   ei32 = (const int*)d_in[1];     // [2, N_EDGES] int32 or int64
    const float* W    = (const float*)d_in[2];   // [NF, NF]
    const float* b    = (const float*)d_in[3];   // [NF]
    float*       out  = (float*)d_out;           // [N_NODES, NF]

    detect_idx_kernel<<<1, 32>>>(ei32);
    zero_cnt_kernel<<<(N_NODES + 255) / 256, 256>>>();
    count_deg_kernel<<<(N_EDGES / 4 + 255) / 256, 256>>>(ei32);
    scan_a_kernel<<<SCAN_NBLK, SCAN_B>>>();
    scan_b_kernel<<<1, 32>>>();
    scan_c_kernel<<<(N_NODES + 255) / 256, 256>>>();
    place_kernel<<<(N_EDGES / 4 + 255) / 256, 256>>>(ei32);
    gemm_kernel<<<N_NODES / GEMM_ROWS, 128>>>(x, W);
    gather_kernel<<<N_NODES, 128>>>(b, out);
}